// round 3
// baseline (speedup 1.0000x reference)
#include <cuda_runtime.h>
#include <math.h>

#define N_SLOTS 16384
#define MD      512
#define CTRL    1024
#define OUTF    (3*MD + 6)   // 1542
#define EPSF    1e-16f

// ---- scratch (device globals: no allocation allowed) ----
__device__ float g_o[OUTF];
__device__ float g_e[MD];
__device__ float g_a[MD];
__device__ float g_expwc[N_SLOTS];
__device__ float g_wp[N_SLOTS];
__device__ float g_partialB[2048];
__device__ float g_partialC[64];
__device__ float g_params[7];   // beta, g, s0, s1, s2, gamma, k_norm
__device__ float g_inv_sumexp;
__device__ float g_inv_sumwp;
__device__ int   g_cnt0;        // zero-initialized; each user resets after use
__device__ int   g_cnt1;
__device__ int   g_cnt2;

__device__ __forceinline__ float softplusf(float x) {
    return x > 20.f ? x : log1pf(expf(x));
}

// ---- K1: o = emb @ W^T + b (warp/row); last block derives params ----
__global__ void k_proj(const float* __restrict__ emb,
                       const float* __restrict__ W,
                       const float* __restrict__ b) {
    __shared__ float red[4];
    __shared__ int isLast;
    int warp = threadIdx.x >> 5;
    int lane = threadIdx.x & 31;
    int row  = blockIdx.x * 4 + warp;
    if (row < OUTF) {
        const float4* W4 = (const float4*)(W + (size_t)row * CTRL);
        const float4* e4 = (const float4*)emb;
        float sum = 0.f;
#pragma unroll
        for (int j = 0; j < 8; j++) {
            float4 wv = W4[lane + 32*j];
            float4 ev = e4[lane + 32*j];
            sum += wv.x*ev.x + wv.y*ev.y + wv.z*ev.z + wv.w*ev.w;
        }
#pragma unroll
        for (int off = 16; off; off >>= 1) sum += __shfl_down_sync(0xffffffffu, sum, off);
        if (lane == 0) g_o[row] = sum + b[row];
    }
    __syncthreads();
    if (threadIdx.x == 0) {
        __threadfence();
        int t = atomicAdd(&g_cnt0, 1);
        isLast = (t == gridDim.x - 1);
        if (isLast) g_cnt0 = 0;   // reset for next graph replay
    }
    __syncthreads();
    if (!isLast) return;
    // --- final block: e/a aligned copies + knorm + scalar params ---
    int t = threadIdx.x;  // 128 threads
    float ss = 0.f;
#pragma unroll
    for (int i = 0; i < 4; i++) {
        int idx = t + 128*i;
        float v = g_o[idx];
        ss += v * v;
        g_e[idx] = g_o[MD + 6 + idx];
        g_a[idx] = g_o[2*MD + 6 + idx];
    }
#pragma unroll
    for (int off = 16; off; off >>= 1) ss += __shfl_down_sync(0xffffffffu, ss, off);
    if (lane == 0) red[warp] = ss;
    __syncthreads();
    if (t == 0) {
        float knorm = sqrtf(red[0] + red[1] + red[2] + red[3]);
        float beta  = softplusf(g_o[MD]);
        float gg    = 1.f / (1.f + expf(-g_o[MD+1]));
        float x0 = g_o[MD+2], x1 = g_o[MD+3], x2 = g_o[MD+4];
        float m  = fmaxf(x0, fmaxf(x1, x2));
        float e0 = expf(x0-m), e1 = expf(x1-m), e2 = expf(x2-m);
        float inv = 1.f / (e0 + e1 + e2);
        float gamma = 1.f + softplusf(g_o[MD+5]);
        g_params[0] = beta; g_params[1] = gg;
        g_params[2] = e0*inv; g_params[3] = e1*inv; g_params[4] = e2*inv;
        g_params[5] = gamma; g_params[6] = knorm;
    }
}

// ---- K2: cosine sim + exp(beta*sim); last block reduces -> inv_sumexp ----
__global__ void k_sim(const float* __restrict__ mem) {
    __shared__ float sk[MD];
    __shared__ float wsum[8];
    __shared__ int isLast;
    int tid = threadIdx.x;
    for (int i = tid; i < MD; i += 256) sk[i] = g_o[i];
    __syncthreads();
    int wid = tid >> 5, lane = tid & 31;
    int row = blockIdx.x * 8 + wid;
    const float4* m4 = (const float4*)(mem + (size_t)row * MD);
    const float4* k4 = (const float4*)sk;
    float dot = 0.f, nrm = 0.f;
#pragma unroll
    for (int j = 0; j < 4; j++) {
        float4 mv = m4[lane + 32*j];
        float4 kv = k4[lane + 32*j];
        dot += mv.x*kv.x + mv.y*kv.y + mv.z*kv.z + mv.w*kv.w;
        nrm += mv.x*mv.x + mv.y*mv.y + mv.z*mv.z + mv.w*mv.w;
    }
#pragma unroll
    for (int off = 16; off; off >>= 1) {
        dot += __shfl_down_sync(0xffffffffu, dot, off);
        nrm += __shfl_down_sync(0xffffffffu, nrm, off);
    }
    if (lane == 0) {
        float denom = g_params[6] * sqrtf(nrm) + EPSF;
        // sim in [-1,1], beta = softplus(~N(0,1)) is modest: exp cannot overflow
        float ex = expf(g_params[0] * dot / denom);
        g_expwc[row] = ex;
        wsum[wid] = ex;
    }
    __syncthreads();
    if (tid == 0) {
        float s = 0.f;
#pragma unroll
        for (int i = 0; i < 8; i++) s += wsum[i];
        g_partialB[blockIdx.x] = s;
        __threadfence();
        int t = atomicAdd(&g_cnt1, 1);
        isLast = (t == gridDim.x - 1);
        if (isLast) g_cnt1 = 0;
    }
    __syncthreads();
    if (!isLast) return;
    // --- final block: deterministic reduce of 2048 partials ---
    float s = 0.f;
#pragma unroll
    for (int i = 0; i < 8; i++) s += g_partialB[tid + 256*i];
#pragma unroll
    for (int off = 16; off; off >>= 1) s += __shfl_down_sync(0xffffffffu, s, off);
    if (lane == 0) wsum[wid] = s;
    __syncthreads();
    if (tid == 0) {
        float tot = 0.f;
#pragma unroll
        for (int i = 0; i < 8; i++) tot += wsum[i];
        g_inv_sumexp = 1.f / tot;
    }
}

// ---- K3: interpolate + shift + sharpen; last block reduces -> inv_sumwp ----
__global__ void k_shiftpow(const float* __restrict__ w_prev) {
    __shared__ float red[256];
    __shared__ int isLast;
    int tid = threadIdx.x;
    int i = blockIdx.x * 256 + tid;
    float gg = g_params[1], s0 = g_params[2], s1 = g_params[3],
          s2 = g_params[4], gamma = g_params[5];
    float ise = g_inv_sumexp;
    float omg = 1.f - gg;
    int im = (i == 0) ? N_SLOTS-1 : i-1;
    int ip = (i == N_SLOTS-1) ? 0 : i+1;
    float wgm = gg * g_expwc[im] * ise + omg * w_prev[im];
    float wgc = gg * g_expwc[i ] * ise + omg * w_prev[i ];
    float wgp = gg * g_expwc[ip] * ise + omg * w_prev[ip];
    float ws = s0*wgm + s1*wgc + s2*wgp;
    float wp = exp2f(gamma * log2f(ws + EPSF));   // ws+EPS > 0 always
    g_wp[i] = wp;
    red[tid] = wp;
    __syncthreads();
    for (int s = 128; s; s >>= 1) { if (tid < s) red[tid] += red[tid+s]; __syncthreads(); }
    if (tid == 0) {
        g_partialC[blockIdx.x] = red[0];
        __threadfence();
        int t = atomicAdd(&g_cnt2, 1);
        isLast = (t == gridDim.x - 1);
        if (isLast) g_cnt2 = 0;
    }
    __syncthreads();
    if (!isLast) return;
    // --- final block: reduce 64 partials ---
    float s = (tid < 64) ? g_partialC[tid] : 0.f;
#pragma unroll
    for (int off = 16; off; off >>= 1) s += __shfl_down_sync(0xffffffffu, s, off);
    if ((tid & 31) == 0) red[tid >> 5] = s;
    __syncthreads();
    if (tid == 0) g_inv_sumwp = 1.f / (red[0] + red[1]);
}

// ---- K4: memory update + w output (2 rows per 256-thread block) ----
__global__ void k_update(const float* __restrict__ mem, float* __restrict__ out) {
    int tid = threadIdx.x;
    int row = blockIdx.x * 2 + (tid >> 7);
    int col = tid & 127;
    float wv = g_wp[row] * g_inv_sumwp;
    if (col == 0) out[row] = wv;
    const float4* m4 = (const float4*)(mem + (size_t)row * MD);
    const float4* e4 = (const float4*)g_e;
    const float4* a4 = (const float4*)g_a;
    float4* o4 = (float4*)(out + N_SLOTS + (size_t)row * MD);
    float4 m = m4[col], e = e4[col], a = a4[col];
    float4 r;
    r.x = m.x * (1.f - wv*e.x) + wv*a.x;
    r.y = m.y * (1.f - wv*e.y) + wv*a.y;
    r.z = m.z * (1.f - wv*e.z) + wv*a.z;
    r.w = m.w * (1.f - wv*e.w) + wv*a.w;
    o4[col] = r;
}

extern "C" void kernel_launch(void* const* d_in, const int* in_sizes, int n_in,
                              void* d_out, int out_size) {
    const float* emb    = (const float*)d_in[0];   // (1, 1024)
    const float* w_prev = (const float*)d_in[1];   // (1, 16384)
    const float* mem    = (const float*)d_in[2];   // (16384, 512)
    const float* W      = (const float*)d_in[3];   // (1542, 1024)
    const float* b      = (const float*)d_in[4];   // (1542,)
    float* out = (float*)d_out;                    // [w(16384) | new_memory(16384*512)]

    k_proj<<<(OUTF + 3) / 4, 128>>>(emb, W, b);
    k_sim<<<N_SLOTS / 8, 256>>>(mem);
    k_shiftpow<<<N_SLOTS / 256, 256>>>(w_prev);
    k_update<<<N_SLOTS / 2, 256>>>(mem, out);
}

// round 4
// speedup vs baseline: 1.5740x; 1.5740x over previous
#include <cuda_runtime.h>
#include <math.h>

#define N_SLOTS 16384
#define MD      512
#define CTRL    1024
#define OUTF    (3*MD + 6)   // 1542
#define EPSF    1e-16f

// ---- scratch (device globals: no allocation allowed) ----
__device__ float g_o[MD + 6];     // k (512) + 6 scalars
__device__ float g_e[MD];
__device__ float g_a[MD];
__device__ float g_expwc[N_SLOTS];
__device__ float g_wp[N_SLOTS];
__device__ float g_partialB[2048];
__device__ float g_partialC[64];

__device__ __forceinline__ float softplusf(float x) {
    return x > 20.f ? x : log1pf(expf(x));
}

// ---- K1: o = emb @ W^T + b (one warp per output row).
//      Rows [0,518) -> g_o ; e rows -> g_e (aligned) ; a rows -> g_a. ----
__global__ void k_proj(const float* __restrict__ emb,
                       const float* __restrict__ W,
                       const float* __restrict__ b) {
    int warp = threadIdx.x >> 5;
    int lane = threadIdx.x & 31;
    int row  = blockIdx.x * 4 + warp;
    if (row >= OUTF) return;
    const float4* W4 = (const float4*)(W + (size_t)row * CTRL);
    const float4* e4 = (const float4*)emb;
    float sum = 0.f;
#pragma unroll
    for (int j = 0; j < 8; j++) {
        float4 wv = W4[lane + 32*j];
        float4 ev = e4[lane + 32*j];
        sum += wv.x*ev.x + wv.y*ev.y + wv.z*ev.z + wv.w*ev.w;
    }
#pragma unroll
    for (int off = 16; off; off >>= 1) sum += __shfl_down_sync(0xffffffffu, sum, off);
    if (lane == 0) {
        float o = sum + b[row];
        if (row < MD + 6)            g_o[row] = o;
        else if (row < 2*MD + 6)     g_e[row - (MD + 6)] = o;
        else                         g_a[row - (2*MD + 6)] = o;
    }
}

// ---- K2: cosine sim + exp(beta*sim). Each block redundantly computes
//      knorm & beta from g_o (deterministic). 8 rows/block. ----
__global__ void k_sim(const float* __restrict__ mem) {
    __shared__ float sk[MD];
    __shared__ float sred[8];
    __shared__ float s_beta, s_knorm;
    int tid = threadIdx.x;
    int wid = tid >> 5, lane = tid & 31;

    float ksq = 0.f;
#pragma unroll
    for (int i = tid; i < MD; i += 256) { float v = g_o[i]; sk[i] = v; ksq += v*v; }
#pragma unroll
    for (int off = 16; off; off >>= 1) ksq += __shfl_down_sync(0xffffffffu, ksq, off);
    if (lane == 0) sred[wid] = ksq;
    __syncthreads();
    if (tid == 0) {
        float s = 0.f;
#pragma unroll
        for (int i = 0; i < 8; i++) s += sred[i];
        s_knorm = sqrtf(s);
        s_beta  = softplusf(g_o[MD]);
    }

    int row = blockIdx.x * 8 + wid;
    const float4* m4 = (const float4*)(mem + (size_t)row * MD);
    const float4* k4 = (const float4*)sk;
    float dot = 0.f, nrm = 0.f;
#pragma unroll
    for (int j = 0; j < 4; j++) {
        float4 mv = m4[lane + 32*j];
        float4 kv = k4[lane + 32*j];
        dot += mv.x*kv.x + mv.y*kv.y + mv.z*kv.z + mv.w*kv.w;
        nrm += mv.x*mv.x + mv.y*mv.y + mv.z*mv.z + mv.w*mv.w;
    }
#pragma unroll
    for (int off = 16; off; off >>= 1) {
        dot += __shfl_down_sync(0xffffffffu, dot, off);
        nrm += __shfl_down_sync(0xffffffffu, nrm, off);
    }
    __syncthreads();   // s_beta / s_knorm ready
    if (lane == 0) {
        float denom = s_knorm * sqrtf(nrm) + EPSF;
        // sim in [-1,1], beta = softplus(~N(0,1)) modest: exp cannot overflow
        float ex = expf(s_beta * dot / denom);
        g_expwc[row] = ex;
        sred[wid] = ex;
    }
    __syncthreads();
    if (tid == 0) {
        float s = 0.f;
#pragma unroll
        for (int i = 0; i < 8; i++) s += sred[i];
        g_partialB[blockIdx.x] = s;
    }
}

// ---- K3: interpolate + shift + sharpen. Each block redundantly reduces
//      the 2048 exp-partials and derives scalars. 64 blocks x 256. ----
__global__ void k_shiftpow(const float* __restrict__ w_prev) {
    __shared__ float red[256];
    __shared__ float sc[6];   // ise, g, s0, s1, s2, gamma
    int tid = threadIdx.x;

    float s = 0.f;
#pragma unroll
    for (int j = 0; j < 8; j++) s += g_partialB[tid + 256*j];
    red[tid] = s;
    __syncthreads();
    for (int st = 128; st; st >>= 1) { if (tid < st) red[tid] += red[tid+st]; __syncthreads(); }
    if (tid == 0) {
        sc[0] = 1.f / red[0];
        sc[1] = 1.f / (1.f + expf(-g_o[MD+1]));
        float x0 = g_o[MD+2], x1 = g_o[MD+3], x2 = g_o[MD+4];
        float m  = fmaxf(x0, fmaxf(x1, x2));
        float e0 = expf(x0-m), e1 = expf(x1-m), e2 = expf(x2-m);
        float inv = 1.f / (e0 + e1 + e2);
        sc[2] = e0*inv; sc[3] = e1*inv; sc[4] = e2*inv;
        sc[5] = 1.f + softplusf(g_o[MD+5]);
    }
    __syncthreads();

    float ise = sc[0], gg = sc[1], s0 = sc[2], s1 = sc[3], s2 = sc[4], gamma = sc[5];
    float omg = 1.f - gg;
    int i = blockIdx.x * 256 + tid;
    int im = (i == 0) ? N_SLOTS-1 : i-1;
    int ip = (i == N_SLOTS-1) ? 0 : i+1;
    float wgm = gg * g_expwc[im] * ise + omg * w_prev[im];
    float wgc = gg * g_expwc[i ] * ise + omg * w_prev[i ];
    float wgp = gg * g_expwc[ip] * ise + omg * w_prev[ip];
    float ws = s0*wgm + s1*wgc + s2*wgp;
    float wp = exp2f(gamma * log2f(ws + EPSF));   // ws+EPS > 0 always
    g_wp[i] = wp;
    red[tid] = wp;
    __syncthreads();
    for (int st = 128; st; st >>= 1) { if (tid < st) red[tid] += red[tid+st]; __syncthreads(); }
    if (tid == 0) g_partialC[blockIdx.x] = red[0];
}

// ---- K4: memory update + w output. 8 rows per 256-thread block;
//      e/a held in registers across the 4-row loop. ----
__global__ void k_update(const float* __restrict__ mem, float* __restrict__ out) {
    __shared__ float sw[8];
    __shared__ float tmp2[2];
    __shared__ float s_inv;
    int tid = threadIdx.x;
    int lane = tid & 31;
    int base = blockIdx.x * 8;

    // redundant deterministic reduce of 64 wp-partials (threads 0..63)
    if (tid < 64) {
        float s = g_partialC[tid];
#pragma unroll
        for (int off = 16; off; off >>= 1) s += __shfl_down_sync(0xffffffffu, s, off);
        if (lane == 0) tmp2[tid >> 5] = s;
    }
    if (tid < 8) sw[tid] = g_wp[base + tid];
    __syncthreads();
    if (tid == 0) s_inv = 1.f / (tmp2[0] + tmp2[1]);
    __syncthreads();
    float inv = s_inv;

    if (tid < 8) out[base + tid] = sw[tid] * inv;

    int c    = tid & 127;   // float4 column
    int half = tid >> 7;    // 0/1
    const float4* e4 = (const float4*)g_e;
    const float4* a4 = (const float4*)g_a;
    float4 e = e4[c], a = a4[c];
    float* nm = out + N_SLOTS;
#pragma unroll
    for (int it = 0; it < 4; it++) {
        int row = base + half + 2*it;
        float wv = sw[half + 2*it] * inv;
        const float4* m4 = (const float4*)(mem + (size_t)row * MD);
        float4* o4 = (float4*)(nm + (size_t)row * MD);
        float4 m = m4[c];
        float4 r;
        r.x = m.x * (1.f - wv*e.x) + wv*a.x;
        r.y = m.y * (1.f - wv*e.y) + wv*a.y;
        r.z = m.z * (1.f - wv*e.z) + wv*a.z;
        r.w = m.w * (1.f - wv*e.w) + wv*a.w;
        o4[c] = r;
    }
}

extern "C" void kernel_launch(void* const* d_in, const int* in_sizes, int n_in,
                              void* d_out, int out_size) {
    const float* emb    = (const float*)d_in[0];   // (1, 1024)
    const float* w_prev = (const float*)d_in[1];   // (1, 16384)
    const float* mem    = (const float*)d_in[2];   // (16384, 512)
    const float* W      = (const float*)d_in[3];   // (1542, 1024)
    const float* b      = (const float*)d_in[4];   // (1542,)
    float* out = (float*)d_out;                    // [w(16384) | new_memory(16384*512)]

    k_proj<<<(OUTF + 3) / 4, 128>>>(emb, W, b);
    k_sim<<<N_SLOTS / 8, 256>>>(mem);
    k_shiftpow<<<N_SLOTS / 256, 256>>>(w_prev);
    k_update<<<N_SLOTS / 8, 256>>>(mem, out);
}

// round 6
// speedup vs baseline: 1.6951x; 1.0769x over previous
#include <cuda_runtime.h>
#include <math.h>

#define N_SLOTS 16384
#define MD      512
#define CTRL    1024
#define OUTF    (3*MD + 6)   // 1542
#define EPSF    1e-16f

// ---- scratch (device globals: no allocation allowed) ----
__device__ float g_o[MD + 6];     // k (512) + 6 scalars
__device__ float g_e[MD];
__device__ float g_a[MD];
__device__ float g_expwc[N_SLOTS];
__device__ float g_wp[N_SLOTS];
__device__ float g_partialB[1024];
__device__ float g_partialC[64];

__device__ __forceinline__ float softplusf(float x) {
    return x > 20.f ? x : log1pf(expf(x));
}

// ---- K1: o = emb @ W^T + b (one warp per output row).
//      Rows [0,518) -> g_o ; e rows -> g_e (aligned) ; a rows -> g_a. ----
__global__ void k_proj(const float* __restrict__ emb,
                       const float* __restrict__ W,
                       const float* __restrict__ b) {
    int warp = threadIdx.x >> 5;
    int lane = threadIdx.x & 31;
    int row  = blockIdx.x * 4 + warp;
    if (row >= OUTF) return;
    const float4* W4 = (const float4*)(W + (size_t)row * CTRL);
    const float4* e4 = (const float4*)emb;
    float sum = 0.f;
#pragma unroll
    for (int j = 0; j < 8; j++) {
        float4 wv = W4[lane + 32*j];
        float4 ev = e4[lane + 32*j];
        sum += wv.x*ev.x + wv.y*ev.y + wv.z*ev.z + wv.w*ev.w;
    }
#pragma unroll
    for (int off = 16; off; off >>= 1) sum += __shfl_down_sync(0xffffffffu, sum, off);
    if (lane == 0) {
        float o = sum + b[row];
        if (row < MD + 6)            g_o[row] = o;
        else if (row < 2*MD + 6)     g_e[row - (MD + 6)] = o;
        else                         g_a[row - (2*MD + 6)] = o;
    }
}

// ---- K2: cosine sim + exp(beta*sim). 2 rows per warp (8 outstanding
//      LDG.128/thread). Each block redundantly derives knorm/beta. ----
__global__ void k_sim(const float* __restrict__ mem) {
    __shared__ float sk[MD];
    __shared__ float sred[16];
    __shared__ float s_beta, s_knorm;
    int tid = threadIdx.x;
    int wid = tid >> 5, lane = tid & 31;

    // front-batch the 8 global row loads (independent of k/smem work)
    int row0 = blockIdx.x * 16 + wid;        // rows row0 and row0+8
    const float4* mA = (const float4*)(mem + (size_t)row0 * MD);
    const float4* mB = (const float4*)(mem + (size_t)(row0 + 8) * MD);
    float4 va[4], vb[4];
#pragma unroll
    for (int j = 0; j < 4; j++) va[j] = mA[lane + 32*j];
#pragma unroll
    for (int j = 0; j < 4; j++) vb[j] = mB[lane + 32*j];

    float ksq = 0.f;
#pragma unroll
    for (int i = tid; i < MD; i += 256) { float v = g_o[i]; sk[i] = v; ksq += v*v; }
#pragma unroll
    for (int off = 16; off; off >>= 1) ksq += __shfl_down_sync(0xffffffffu, ksq, off);
    if (lane == 0) sred[wid] = ksq;
    __syncthreads();
    if (tid == 0) {
        float s = 0.f;
#pragma unroll
        for (int i = 0; i < 8; i++) s += sred[i];
        s_knorm = sqrtf(s);
        s_beta  = softplusf(g_o[MD]);
    }
    __syncthreads();   // sk + s_beta/s_knorm ready

    const float4* k4 = (const float4*)sk;
    float dotA = 0.f, nrmA = 0.f, dotB = 0.f, nrmB = 0.f;
#pragma unroll
    for (int j = 0; j < 4; j++) {
        float4 kv = k4[lane + 32*j];
        dotA += va[j].x*kv.x + va[j].y*kv.y + va[j].z*kv.z + va[j].w*kv.w;
        nrmA += va[j].x*va[j].x + va[j].y*va[j].y + va[j].z*va[j].z + va[j].w*va[j].w;
        dotB += vb[j].x*kv.x + vb[j].y*kv.y + vb[j].z*kv.z + vb[j].w*kv.w;
        nrmB += vb[j].x*vb[j].x + vb[j].y*vb[j].y + vb[j].z*vb[j].z + vb[j].w*vb[j].w;
    }
#pragma unroll
    for (int off = 16; off; off >>= 1) {
        dotA += __shfl_down_sync(0xffffffffu, dotA, off);
        nrmA += __shfl_down_sync(0xffffffffu, nrmA, off);
        dotB += __shfl_down_sync(0xffffffffu, dotB, off);
        nrmB += __shfl_down_sync(0xffffffffu, nrmB, off);
    }
    if (lane == 0) {
        // sim in [-1,1], beta = softplus(~N(0,1)) modest: exp cannot overflow
        float exA = expf(s_beta * dotA / (s_knorm * sqrtf(nrmA) + EPSF));
        float exB = expf(s_beta * dotB / (s_knorm * sqrtf(nrmB) + EPSF));
        g_expwc[row0]     = exA;
        g_expwc[row0 + 8] = exB;
        sred[wid]     = exA;
        sred[wid + 8] = exB;
    }
    __syncthreads();
    if (tid == 0) {
        float s = 0.f;
#pragma unroll
        for (int i = 0; i < 16; i++) s += sred[i];
        g_partialB[blockIdx.x] = s;
    }
}

// ---- K3: interpolate + shift + sharpen. Each block redundantly reduces
//      the 1024 exp-partials and derives scalars. 64 blocks x 256. ----
__global__ void k_shiftpow(const float* __restrict__ w_prev) {
    __shared__ float red[256];
    __shared__ float sc[6];   // ise, g, s0, s1, s2, gamma
    int tid = threadIdx.x;

    float s = 0.f;
#pragma unroll
    for (int j = 0; j < 4; j++) s += g_partialB[tid + 256*j];
    red[tid] = s;
    __syncthreads();
    for (int st = 128; st; st >>= 1) { if (tid < st) red[tid] += red[tid+st]; __syncthreads(); }
    if (tid == 0) {
        sc[0] = 1.f / red[0];
        sc[1] = 1.f / (1.f + expf(-g_o[MD+1]));
        float x0 = g_o[MD+2], x1 = g_o[MD+3], x2 = g_o[MD+4];
        float m  = fmaxf(x0, fmaxf(x1, x2));
        float e0 = expf(x0-m), e1 = expf(x1-m), e2 = expf(x2-m);
        float inv = 1.f / (e0 + e1 + e2);
        sc[2] = e0*inv; sc[3] = e1*inv; sc[4] = e2*inv;
        sc[5] = 1.f + softplusf(g_o[MD+5]);
    }
    __syncthreads();

    float ise = sc[0], gg = sc[1], s0 = sc[2], s1 = sc[3], s2 = sc[4], gamma = sc[5];
    float omg = 1.f - gg;
    int i = blockIdx.x * 256 + tid;
    int im = (i == 0) ? N_SLOTS-1 : i-1;
    int ip = (i == N_SLOTS-1) ? 0 : i+1;
    float wgm = gg * g_expwc[im] * ise + omg * w_prev[im];
    float wgc = gg * g_expwc[i ] * ise + omg * w_prev[i ];
    float wgp = gg * g_expwc[ip] * ise + omg * w_prev[ip];
    float ws = s0*wgm + s1*wgc + s2*wgp;
    float wp = exp2f(gamma * log2f(ws + EPSF));   // ws+EPS > 0 always
    g_wp[i] = wp;
    red[tid] = wp;
    __syncthreads();
    for (int st = 128; st; st >>= 1) { if (tid < st) red[tid] += red[tid+st]; __syncthreads(); }
    if (tid == 0) g_partialC[blockIdx.x] = red[0];
}

// ---- K4: memory update + w output. 8 rows per 256-thread block;
//      e/a in registers; 4 hoisted batched row-loads; streaming stores. ----
__global__ void k_update(const float* __restrict__ mem, float* __restrict__ out) {
    __shared__ float sw[8];
    __shared__ float tmp2[2];
    __shared__ float s_inv;
    int tid = threadIdx.x;
    int lane = tid & 31;
    int base = blockIdx.x * 8;

    int c    = tid & 127;   // float4 column
    int half = tid >> 7;    // 0/1

    // hoist the 4 independent row loads FIRST (overlap with reduction below)
    float4 m[4];
#pragma unroll
    for (int it = 0; it < 4; it++) {
        int row = base + half + 2*it;
        m[it] = ((const float4*)(mem + (size_t)row * MD))[c];
    }
    const float4* e4 = (const float4*)g_e;
    const float4* a4 = (const float4*)g_a;
    float4 e = e4[c], a = a4[c];

    // redundant deterministic reduce of 64 wp-partials (threads 0..63)
    if (tid < 64) {
        float s = g_partialC[tid];
#pragma unroll
        for (int off = 16; off; off >>= 1) s += __shfl_down_sync(0xffffffffu, s, off);
        if (lane == 0) tmp2[tid >> 5] = s;
    }
    if (tid < 8) sw[tid] = g_wp[base + tid];
    __syncthreads();
    if (tid == 0) s_inv = 1.f / (tmp2[0] + tmp2[1]);
    __syncthreads();
    float inv = s_inv;

    if (tid < 8) out[base + tid] = sw[tid] * inv;

    float* nm = out + N_SLOTS;
#pragma unroll
    for (int it = 0; it < 4; it++) {
        int row = base + half + 2*it;
        float wv = sw[half + 2*it] * inv;
        float4 r;
        r.x = m[it].x * (1.f - wv*e.x) + wv*a.x;
        r.y = m[it].y * (1.f - wv*e.y) + wv*a.y;
        r.z = m[it].z * (1.f - wv*e.z) + wv*a.z;
        r.w = m[it].w * (1.f - wv*e.w) + wv*a.w;
        __stcs((float4*)(nm + (size_t)row * MD) + c, r);   // streaming: never re-read
    }
}

extern "C" void kernel_launch(void* const* d_in, const int* in_sizes, int n_in,
                              void* d_out, int out_size) {
    const float* emb    = (const float*)d_in[0];   // (1, 1024)
    const float* w_prev = (const float*)d_in[1];   // (1, 16384)
    const float* mem    = (const float*)d_in[2];   // (16384, 512)
    const float* W      = (const float*)d_in[3];   // (1542, 1024)
    const float* b      = (const float*)d_in[4];   // (1542,)
    float* out = (float*)d_out;                    // [w(16384) | new_memory(16384*512)]

    k_proj<<<(OUTF + 3) / 4, 128>>>(emb, W, b);
    k_sim<<<N_SLOTS / 16, 256>>>(mem);
    k_shiftpow<<<N_SLOTS / 256, 256>>>(w_prev);
    k_update<<<N_SLOTS / 8, 256>>>(mem, out);
}

// round 7
// speedup vs baseline: 1.7283x; 1.0196x over previous
#include <cuda_runtime.h>
#include <math.h>

#define N_SLOTS 16384
#define MD      512
#define CTRL    1024
#define OUTF    (3*MD + 6)   // 1542
#define EPSF    1e-16f

// ---- scratch (device globals: no allocation allowed) ----
__device__ float g_o[MD + 6];     // k (512) + 6 scalars
__device__ float g_e[MD];
__device__ float g_a[MD];
__device__ float g_expwc[N_SLOTS];
__device__ float g_wp[N_SLOTS];
__device__ float g_partialB[1024];
__device__ float g_partialC[64];

__device__ __forceinline__ float softplusf(float x) {
    return x > 20.f ? x : log1pf(expf(x));
}

// ---- K1: o = emb @ W^T + b (one warp per output row).
//      Rows [0,518) -> g_o ; e rows -> g_e (aligned) ; a rows -> g_a. ----
__global__ void k_proj(const float* __restrict__ emb,
                       const float* __restrict__ W,
                       const float* __restrict__ b) {
    int warp = threadIdx.x >> 5;
    int lane = threadIdx.x & 31;
    int row  = blockIdx.x * 4 + warp;
    if (row >= OUTF) return;
    const float4* W4 = (const float4*)(W + (size_t)row * CTRL);
    const float4* e4 = (const float4*)emb;
    float sum = 0.f;
#pragma unroll
    for (int j = 0; j < 8; j++) {
        float4 wv = W4[lane + 32*j];
        float4 ev = e4[lane + 32*j];
        sum += wv.x*ev.x + wv.y*ev.y + wv.z*ev.z + wv.w*ev.w;
    }
#pragma unroll
    for (int off = 16; off; off >>= 1) sum += __shfl_down_sync(0xffffffffu, sum, off);
    if (lane == 0) {
        float o = sum + b[row];
        if (row < MD + 6)            g_o[row] = o;
        else if (row < 2*MD + 6)     g_e[row - (MD + 6)] = o;
        else                         g_a[row - (2*MD + 6)] = o;
    }
}

// ---- K2: cosine sim + exp(beta*sim). 2 rows per warp (8 outstanding
//      LDG.128/thread, front-batched). Block derives knorm/beta itself. ----
__global__ void k_sim(const float* __restrict__ mem) {
    __shared__ float sk[MD];
    __shared__ float sred[16];
    __shared__ float s_beta, s_knorm;
    int tid = threadIdx.x;
    int wid = tid >> 5, lane = tid & 31;

    // front-batch the 8 global row loads (independent of k/smem work)
    int row0 = blockIdx.x * 16 + wid;        // rows row0 and row0+8
    const float4* mA = (const float4*)(mem + (size_t)row0 * MD);
    const float4* mB = (const float4*)(mem + (size_t)(row0 + 8) * MD);
    float4 va[4], vb[4];
#pragma unroll
    for (int j = 0; j < 4; j++) va[j] = mA[lane + 32*j];
#pragma unroll
    for (int j = 0; j < 4; j++) vb[j] = mB[lane + 32*j];

    float ksq = 0.f;
#pragma unroll
    for (int i = tid; i < MD; i += 256) { float v = g_o[i]; sk[i] = v; ksq += v*v; }
#pragma unroll
    for (int off = 16; off; off >>= 1) ksq += __shfl_down_sync(0xffffffffu, ksq, off);
    if (lane == 0) sred[wid] = ksq;
    __syncthreads();
    if (tid == 0) {
        float s = 0.f;
#pragma unroll
        for (int i = 0; i < 8; i++) s += sred[i];
        s_knorm = sqrtf(s);
        s_beta  = softplusf(g_o[MD]);
    }
    __syncthreads();   // sk + s_beta/s_knorm ready

    const float4* k4 = (const float4*)sk;
    float dotA = 0.f, nrmA = 0.f, dotB = 0.f, nrmB = 0.f;
#pragma unroll
    for (int j = 0; j < 4; j++) {
        float4 kv = k4[lane + 32*j];
        dotA += va[j].x*kv.x + va[j].y*kv.y + va[j].z*kv.z + va[j].w*kv.w;
        nrmA += va[j].x*va[j].x + va[j].y*va[j].y + va[j].z*va[j].z + va[j].w*va[j].w;
        dotB += vb[j].x*kv.x + vb[j].y*kv.y + vb[j].z*kv.z + vb[j].w*kv.w;
        nrmB += vb[j].x*vb[j].x + vb[j].y*vb[j].y + vb[j].z*vb[j].z + vb[j].w*vb[j].w;
    }
#pragma unroll
    for (int off = 16; off; off >>= 1) {
        dotA += __shfl_down_sync(0xffffffffu, dotA, off);
        nrmA += __shfl_down_sync(0xffffffffu, nrmA, off);
        dotB += __shfl_down_sync(0xffffffffu, dotB, off);
        nrmB += __shfl_down_sync(0xffffffffu, nrmB, off);
    }
    if (lane == 0) {
        // sim in [-1,1], beta = softplus(~N(0,1)) modest: exp cannot overflow
        float exA = expf(s_beta * dotA / (s_knorm * sqrtf(nrmA) + EPSF));
        float exB = expf(s_beta * dotB / (s_knorm * sqrtf(nrmB) + EPSF));
        g_expwc[row0]     = exA;
        g_expwc[row0 + 8] = exB;
        sred[wid]     = exA;
        sred[wid + 8] = exB;
    }
    __syncthreads();
    if (tid == 0) {
        float s = 0.f;
#pragma unroll
        for (int i = 0; i < 16; i++) s += sred[i];
        g_partialB[blockIdx.x] = s;
    }
}

// ---- K3: interpolate + shift + sharpen. Each block redundantly reduces
//      the 1024 exp-partials and derives scalars. 64 blocks x 256. ----
__global__ void k_shiftpow(const float* __restrict__ w_prev) {
    __shared__ float red[256];
    __shared__ float sc[6];   // ise, g, s0, s1, s2, gamma
    int tid = threadIdx.x;

    float s = 0.f;
#pragma unroll
    for (int j = 0; j < 4; j++) s += g_partialB[tid + 256*j];
    red[tid] = s;
    __syncthreads();
    for (int st = 128; st; st >>= 1) { if (tid < st) red[tid] += red[tid+st]; __syncthreads(); }
    if (tid == 0) {
        sc[0] = 1.f / red[0];
        sc[1] = 1.f / (1.f + expf(-g_o[MD+1]));
        float x0 = g_o[MD+2], x1 = g_o[MD+3], x2 = g_o[MD+4];
        float m  = fmaxf(x0, fmaxf(x1, x2));
        float e0 = expf(x0-m), e1 = expf(x1-m), e2 = expf(x2-m);
        float inv = 1.f / (e0 + e1 + e2);
        sc[2] = e0*inv; sc[3] = e1*inv; sc[4] = e2*inv;
        sc[5] = 1.f + softplusf(g_o[MD+5]);
    }
    __syncthreads();

    float ise = sc[0], gg = sc[1], s0 = sc[2], s1 = sc[3], s2 = sc[4], gamma = sc[5];
    float omg = 1.f - gg;
    int i = blockIdx.x * 256 + tid;
    int im = (i == 0) ? N_SLOTS-1 : i-1;
    int ip = (i == N_SLOTS-1) ? 0 : i+1;
    float wgm = gg * g_expwc[im] * ise + omg * w_prev[im];
    float wgc = gg * g_expwc[i ] * ise + omg * w_prev[i ];
    float wgp = gg * g_expwc[ip] * ise + omg * w_prev[ip];
    float ws = s0*wgm + s1*wgc + s2*wgp;
    float wp = exp2f(gamma * log2f(ws + EPSF));   // ws+EPS > 0 always
    g_wp[i] = wp;
    red[tid] = wp;
    __syncthreads();
    for (int st = 128; st; st >>= 1) { if (tid < st) red[tid] += red[tid+st]; __syncthreads(); }
    if (tid == 0) g_partialC[blockIdx.x] = red[0];
}

// ---- K4: memory update + w output. BARRIER-FREE, SMEM-FREE.
//      8 rows per 256-thread block; each warp redundantly reduces the 64
//      wp-partials (fixed order -> deterministic); stores issue ASAP. ----
__global__ void k_update(const float* __restrict__ mem, float* __restrict__ out) {
    int tid  = threadIdx.x;
    int lane = tid & 31;
    int base = blockIdx.x * 8;
    int c    = tid & 127;   // float4 column
    int half = tid >> 7;    // 0/1 (warp-uniform)

    // batch the 4 independent row loads FIRST (max outstanding LDG.128)
    float4 m[4];
#pragma unroll
    for (int it = 0; it < 4; it++) {
        int row = base + half + 2*it;
        m[it] = ((const float4*)(mem + (size_t)row * MD))[c];
    }
    float4 e = ((const float4*)g_e)[c];
    float4 a = ((const float4*)g_a)[c];

    // warp-redundant deterministic reduce of 64 wp-partials (no barriers)
    float s = g_partialC[lane] + g_partialC[lane + 32];
#pragma unroll
    for (int off = 16; off; off >>= 1) s += __shfl_xor_sync(0xffffffffu, s, off);
    float inv = 1.f / s;

    // per-row weights: warp-uniform broadcast loads
    float wv[4];
#pragma unroll
    for (int it = 0; it < 4; it++) wv[it] = g_wp[base + half + 2*it] * inv;

    if (tid < 8) out[base + tid] = g_wp[base + tid] * inv;

    float* nm = out + N_SLOTS;
#pragma unroll
    for (int it = 0; it < 4; it++) {
        int row = base + half + 2*it;
        float4 r;
        r.x = m[it].x * (1.f - wv[it]*e.x) + wv[it]*a.x;
        r.y = m[it].y * (1.f - wv[it]*e.y) + wv[it]*a.y;
        r.z = m[it].z * (1.f - wv[it]*e.z) + wv[it]*a.z;
        r.w = m[it].w * (1.f - wv[it]*e.w) + wv[it]*a.w;
        __stcs((float4*)(nm + (size_t)row * MD) + c, r);   // streaming: never re-read
    }
}

extern "C" void kernel_launch(void* const* d_in, const int* in_sizes, int n_in,
                              void* d_out, int out_size) {
    const float* emb    = (const float*)d_in[0];   // (1, 1024)
    const float* w_prev = (const float*)d_in[1];   // (1, 16384)
    const float* mem    = (const float*)d_in[2];   // (16384, 512)
    const float* W      = (const float*)d_in[3];   // (1542, 1024)
    const float* b      = (const float*)d_in[4];   // (1542,)
    float* out = (float*)d_out;                    // [w(16384) | new_memory(16384*512)]

    k_proj<<<(OUTF + 3) / 4, 128>>>(emb, W, b);
    k_sim<<<N_SLOTS / 16, 256>>>(mem);
    k_shiftpow<<<N_SLOTS / 256, 256>>>(w_prev);
    k_update<<<N_SLOTS / 8, 256>>>(mem, out);
}

// round 8
// speedup vs baseline: 1.8811x; 1.0884x over previous
#include <cuda_runtime.h>
#include <math.h>

#define N_SLOTS 16384
#define MD      512
#define CTRL    1024
#define OUTF    (3*MD + 6)   // 1542
#define EPSF    1e-16f

// ---- scratch (device globals: no allocation allowed) ----
__device__ float g_o[MD + 6];     // k (512) + 6 scalars
__device__ float g_e[MD];
__device__ float g_a[MD];
__device__ float g_expwc[N_SLOTS];
__device__ float g_wp[N_SLOTS];
__device__ float g_partialB[1024];
__device__ float g_partialC[64];

__device__ __forceinline__ float softplusf(float x) {
    return x > 20.f ? x : log1pf(expf(x));
}

// ---- K1: o = emb @ W^T + b (one warp per output row).
//      Rows [0,518) -> g_o ; e rows -> g_e (aligned) ; a rows -> g_a. ----
__global__ void k_proj(const float* __restrict__ emb,
                       const float* __restrict__ W,
                       const float* __restrict__ b) {
    int warp = threadIdx.x >> 5;
    int lane = threadIdx.x & 31;
    int row  = blockIdx.x * 4 + warp;
    if (row >= OUTF) return;
    const float4* W4 = (const float4*)(W + (size_t)row * CTRL);
    const float4* e4 = (const float4*)emb;
    float sum = 0.f;
#pragma unroll
    for (int j = 0; j < 8; j++) {
        float4 wv = W4[lane + 32*j];
        float4 ev = e4[lane + 32*j];
        sum += wv.x*ev.x + wv.y*ev.y + wv.z*ev.z + wv.w*ev.w;
    }
#pragma unroll
    for (int off = 16; off; off >>= 1) sum += __shfl_down_sync(0xffffffffu, sum, off);
    if (lane == 0) {
        float o = sum + b[row];
        if (row < MD + 6)            g_o[row] = o;
        else if (row < 2*MD + 6)     g_e[row - (MD + 6)] = o;
        else                         g_a[row - (2*MD + 6)] = o;
    }
}

// ---- K2: cosine sim + exp(beta*sim). 2 rows per warp (8 outstanding
//      LDG.128/thread, front-batched). Block derives knorm/beta itself. ----
__global__ void k_sim(const float* __restrict__ mem) {
    __shared__ float sk[MD];
    __shared__ float sred[16];
    __shared__ float s_beta, s_knorm;
    int tid = threadIdx.x;
    int wid = tid >> 5, lane = tid & 31;

    // front-batch the 8 global row loads (independent of k/smem work)
    int row0 = blockIdx.x * 16 + wid;        // rows row0 and row0+8
    const float4* mA = (const float4*)(mem + (size_t)row0 * MD);
    const float4* mB = (const float4*)(mem + (size_t)(row0 + 8) * MD);
    float4 va[4], vb[4];
#pragma unroll
    for (int j = 0; j < 4; j++) va[j] = mA[lane + 32*j];
#pragma unroll
    for (int j = 0; j < 4; j++) vb[j] = mB[lane + 32*j];

    float ksq = 0.f;
#pragma unroll
    for (int i = tid; i < MD; i += 256) { float v = g_o[i]; sk[i] = v; ksq += v*v; }
#pragma unroll
    for (int off = 16; off; off >>= 1) ksq += __shfl_down_sync(0xffffffffu, ksq, off);
    if (lane == 0) sred[wid] = ksq;
    __syncthreads();
    if (tid == 0) {
        float s = 0.f;
#pragma unroll
        for (int i = 0; i < 8; i++) s += sred[i];
        s_knorm = sqrtf(s);
        s_beta  = softplusf(g_o[MD]);
    }
    __syncthreads();   // sk + s_beta/s_knorm ready

    const float4* k4 = (const float4*)sk;
    float dotA = 0.f, nrmA = 0.f, dotB = 0.f, nrmB = 0.f;
#pragma unroll
    for (int j = 0; j < 4; j++) {
        float4 kv = k4[lane + 32*j];
        dotA += va[j].x*kv.x + va[j].y*kv.y + va[j].z*kv.z + va[j].w*kv.w;
        nrmA += va[j].x*va[j].x + va[j].y*va[j].y + va[j].z*va[j].z + va[j].w*va[j].w;
        dotB += vb[j].x*kv.x + vb[j].y*kv.y + vb[j].z*kv.z + vb[j].w*kv.w;
        nrmB += vb[j].x*vb[j].x + vb[j].y*vb[j].y + vb[j].z*vb[j].z + vb[j].w*vb[j].w;
    }
#pragma unroll
    for (int off = 16; off; off >>= 1) {
        dotA += __shfl_down_sync(0xffffffffu, dotA, off);
        nrmA += __shfl_down_sync(0xffffffffu, nrmA, off);
        dotB += __shfl_down_sync(0xffffffffu, dotB, off);
        nrmB += __shfl_down_sync(0xffffffffu, nrmB, off);
    }
    if (lane == 0) {
        // sim in [-1,1], beta = softplus(~N(0,1)) modest: exp cannot overflow
        float exA = expf(s_beta * dotA / (s_knorm * sqrtf(nrmA) + EPSF));
        float exB = expf(s_beta * dotB / (s_knorm * sqrtf(nrmB) + EPSF));
        g_expwc[row0]     = exA;
        g_expwc[row0 + 8] = exB;
        sred[wid]     = exA;
        sred[wid + 8] = exB;
    }
    __syncthreads();
    if (tid == 0) {
        float s = 0.f;
#pragma unroll
        for (int i = 0; i < 16; i++) s += sred[i];
        g_partialB[blockIdx.x] = s;
    }
}

// ---- K3: interpolate + shift + sharpen. Each block redundantly reduces
//      the 1024 exp-partials and derives scalars. 64 blocks x 256. ----
__global__ void k_shiftpow(const float* __restrict__ w_prev) {
    __shared__ float red[256];
    __shared__ float sc[6];   // ise, g, s0, s1, s2, gamma
    int tid = threadIdx.x;

    float s = 0.f;
#pragma unroll
    for (int j = 0; j < 4; j++) s += g_partialB[tid + 256*j];
    red[tid] = s;
    __syncthreads();
    for (int st = 128; st; st >>= 1) { if (tid < st) red[tid] += red[tid+st]; __syncthreads(); }
    if (tid == 0) {
        sc[0] = 1.f / red[0];
        sc[1] = 1.f / (1.f + expf(-g_o[MD+1]));
        float x0 = g_o[MD+2], x1 = g_o[MD+3], x2 = g_o[MD+4];
        float m  = fmaxf(x0, fmaxf(x1, x2));
        float e0 = expf(x0-m), e1 = expf(x1-m), e2 = expf(x2-m);
        float inv = 1.f / (e0 + e1 + e2);
        sc[2] = e0*inv; sc[3] = e1*inv; sc[4] = e2*inv;
        sc[5] = 1.f + softplusf(g_o[MD+5]);
    }
    __syncthreads();

    float ise = sc[0], gg = sc[1], s0 = sc[2], s1 = sc[3], s2 = sc[4], gamma = sc[5];
    float omg = 1.f - gg;
    int i = blockIdx.x * 256 + tid;
    int im = (i == 0) ? N_SLOTS-1 : i-1;
    int ip = (i == N_SLOTS-1) ? 0 : i+1;
    float wgm = gg * g_expwc[im] * ise + omg * w_prev[im];
    float wgc = gg * g_expwc[i ] * ise + omg * w_prev[i ];
    float wgp = gg * g_expwc[ip] * ise + omg * w_prev[ip];
    float ws = s0*wgm + s1*wgc + s2*wgp;
    float wp = exp2f(gamma * log2f(ws + EPSF));   // ws+EPS > 0 always
    g_wp[i] = wp;
    red[tid] = wp;
    __syncthreads();
    for (int st = 128; st; st >>= 1) { if (tid < st) red[tid] += red[tid+st]; __syncthreads(); }
    if (tid == 0) g_partialC[blockIdx.x] = red[0];
}

// ---- K4: memory update + w output. Barrier-free; 16 rows per 256-thread
//      block, 8 rows/thread -> fewest LSU slots per byte. wp via one
//      predicated load + shfl broadcast. ----
__global__ void k_update(const float* __restrict__ mem, float* __restrict__ out) {
    int tid  = threadIdx.x;
    int lane = tid & 31;
    int base = blockIdx.x * 16;
    int c    = tid & 127;   // float4 column
    int half = tid >> 7;    // 0/1 (warp-uniform)

    // batch all 8 independent row loads first
    float4 m[8];
#pragma unroll
    for (int it = 0; it < 8; it++) {
        int row = base + half + 2*it;
        m[it] = ((const float4*)(mem + (size_t)row * MD))[c];
    }
    float4 e = ((const float4*)g_e)[c];
    float4 a = ((const float4*)g_a)[c];

    // warp-redundant deterministic reduce of 64 wp-partials (no barriers)
    float s = g_partialC[lane] + g_partialC[lane + 32];
#pragma unroll
    for (int off = 16; off; off >>= 1) s += __shfl_xor_sync(0xffffffffu, s, off);
    float inv = 1.f / s;

    // this warp's 8 row-weights: ONE predicated load, then shfl broadcast
    float wp_l = (lane < 8) ? g_wp[base + half + 2*lane] : 0.f;
    float wv[8];
#pragma unroll
    for (int it = 0; it < 8; it++) wv[it] = __shfl_sync(0xffffffffu, wp_l, it) * inv;

    if (tid < 16) out[base + tid] = g_wp[base + tid] * inv;

    float* nm = out + N_SLOTS;
#pragma unroll
    for (int it = 0; it < 8; it++) {
        int row = base + half + 2*it;
        float4 r;
        r.x = m[it].x * (1.f - wv[it]*e.x) + wv[it]*a.x;
        r.y = m[it].y * (1.f - wv[it]*e.y) + wv[it]*a.y;
        r.z = m[it].z * (1.f - wv[it]*e.z) + wv[it]*a.z;
        r.w = m[it].w * (1.f - wv[it]*e.w) + wv[it]*a.w;
        __stcs((float4*)(nm + (size_t)row * MD) + c, r);   // streaming: never re-read
    }
}

extern "C" void kernel_launch(void* const* d_in, const int* in_sizes, int n_in,
                              void* d_out, int out_size) {
    const float* emb    = (const float*)d_in[0];   // (1, 1024)
    const float* w_prev = (const float*)d_in[1];   // (1, 16384)
    const float* mem    = (const float*)d_in[2];   // (16384, 512)
    const float* W      = (const float*)d_in[3];   // (1542, 1024)
    const float* b      = (const float*)d_in[4];   // (1542,)
    float* out = (float*)d_out;                    // [w(16384) | new_memory(16384*512)]

    k_proj<<<(OUTF + 3) / 4, 128>>>(emb, W, b);
    k_sim<<<N_SLOTS / 16, 256>>>(mem);
    k_shiftpow<<<N_SLOTS / 256, 256>>>(w_prev);
    k_update<<<N_SLOTS / 16, 256>>>(mem, out);
}